// round 15
// baseline (speedup 1.0000x reference)
#include <cuda_runtime.h>

#define EDGES   65536
#define NODESN  2048
#define DI      64
#define DOUT    64
#define EPSV    1e-6f
#define CAP     256            // adjacency capacity per node
#define ROWS_A  1792           // rows scanned in part A
#define RCA     28             // rows per tile, part A: 64*28 = 1792
#define RCB     4              // rows per tile, part B: 64*4  = 256

// scratch (no cudaMalloc allowed). Index arrays store idx+1 (0 = not found
// on the very first run; on replays stale values equal the final values and
// all predicates still evaluate identically).
__device__ int    g_si[EDGES];          // src index + 1
__device__ int    g_ti[EDGES];          // tgt index + 1
__device__ int    g_cnt[NODESN];        // per-target count (reset by gather_fin)
__device__ int    g_done[NODESN];       // slots consumed by partial gather
__device__ int    g_adj[NODESN * CAP];  // per-target SOURCE-NODE lists
__device__ float  g_P[NODESN * DOUT];   // x @ Wf_top
__device__ float  g_Q[NODESN * DOUT];   // x @ Wf_bot
__device__ float  g_eu[NODESN];         // exp(x . Ww_top)
__device__ float  g_v[NODESN];          // x . Ww_bot
__device__ float2 g_pacc[NODESN * 32];  // partial numerator per (node, lane)
__device__ float  g_pasum[NODESN];      // partial denominator

// ---------------------------------------------------------------------------
// K0 (k_pre): per-node projections P,Q,exp(u),v. Side stream, hidden under
// scan part A.
// ---------------------------------------------------------------------------
__global__ void __launch_bounds__(256) k_pre(const float* __restrict__ x,
                                             const float* __restrict__ Wf,
                                             const float* __restrict__ Ww) {
    __shared__ float sW[2 * DI * DOUT];   // 32 KB
    __shared__ float sx[DI * 64];         // 16 KB, transposed x tile

    const int tid = threadIdx.x;
    const int n0 = blockIdx.x * 64;

    {
        const float4* Wf4 = (const float4*)Wf;
        float4* sW4 = (float4*)sW;
#pragma unroll
        for (int i = 0; i < 8; ++i)
            sW4[tid + i * 256] = Wf4[tid + i * 256];
    }
    {
        const float4* x4 = (const float4*)x;
#pragma unroll
        for (int i = 0; i < 4; ++i) {
            int idx = tid + i * 256;
            int nl = idx >> 4;
            int kq = idx & 15;
            float4 vv = x4[(n0 + nl) * (DI / 4) + kq];
            sx[(kq * 4 + 0) * 64 + nl] = vv.x;
            sx[(kq * 4 + 1) * 64 + nl] = vv.y;
            sx[(kq * 4 + 2) * 64 + nl] = vv.z;
            sx[(kq * 4 + 3) * 64 + nl] = vv.w;
        }
    }
    __syncthreads();

    const int nl = tid >> 2;
    const int dg = (tid & 3) * 16;

    float accP[16] = {}, accQ[16] = {};
    const float4* sW4 = (const float4*)sW;
#pragma unroll 4
    for (int k = 0; k < DI; ++k) {
        float xv = sx[k * 64 + nl];
        int bP = (k * DOUT + dg) >> 2;
        int bQ = ((DI + k) * DOUT + dg) >> 2;
#pragma unroll
        for (int j = 0; j < 4; ++j) {
            float4 w = sW4[bP + j];
            accP[j * 4 + 0] += xv * w.x; accP[j * 4 + 1] += xv * w.y;
            accP[j * 4 + 2] += xv * w.z; accP[j * 4 + 3] += xv * w.w;
            float4 q = sW4[bQ + j];
            accQ[j * 4 + 0] += xv * q.x; accQ[j * 4 + 1] += xv * q.y;
            accQ[j * 4 + 2] += xv * q.z; accQ[j * 4 + 3] += xv * q.w;
        }
    }
    float4* P4 = (float4*)(g_P + (n0 + nl) * DOUT + dg);
    float4* Q4 = (float4*)(g_Q + (n0 + nl) * DOUT + dg);
#pragma unroll
    for (int j = 0; j < 4; ++j) {
        P4[j] = make_float4(accP[j*4+0], accP[j*4+1], accP[j*4+2], accP[j*4+3]);
        Q4[j] = make_float4(accQ[j*4+0], accQ[j*4+1], accQ[j*4+2], accQ[j*4+3]);
    }

    if (tid < 64) {
        float uu = 0.f, vv = 0.f;
#pragma unroll 8
        for (int k = 0; k < DI; ++k) {
            float xv = sx[k * 64 + tid];
            uu += xv * __ldg(&Ww[k]);
            vv += xv * __ldg(&Ww[DI + k]);
        }
        g_eu[n0 + tid] = expf(uu);
        g_v[n0 + tid]  = vv;
    }
}

// ---------------------------------------------------------------------------
// K1 (k_scan_rows<RC>): fused streaming scan over rows [r0base, r0base+64*RC).
// Full 64-wide X grid (same tile shape as the proven best config); stores
// idx+1 when the one-hot hit is inside this row range. grid (64, 64).
// ---------------------------------------------------------------------------
template <int RC>
__global__ void __launch_bounds__(256) k_scan_rows(const float4* __restrict__ src4,
                                                   const float4* __restrict__ tgt4,
                                                   int r0base) {
    const int g4 = blockIdx.x * blockDim.x + threadIdx.x;   // 0..16383
    const int r0 = r0base + blockIdx.y * RC;
    const int stride4 = EDGES / 4;                          // 16384
    size_t base = (size_t)r0 * stride4 + g4;

    float4 ws = {0.f,0.f,0.f,0.f}, wt = {0.f,0.f,0.f,0.f};  // sum n*v
    float4 ps = {0.f,0.f,0.f,0.f}, pt = {0.f,0.f,0.f,0.f};  // sum v

#pragma unroll 4
    for (int n = 0; n < RC; ++n) {
        float fn = (float)(r0 + n);
        float4 vs = __ldcs(&src4[base]);
        float4 vt = __ldcs(&tgt4[base]);
        base += stride4;
        ws.x += vs.x * fn; ws.y += vs.y * fn; ws.z += vs.z * fn; ws.w += vs.w * fn;
        ps.x += vs.x;      ps.y += vs.y;      ps.z += vs.z;      ps.w += vs.w;
        wt.x += vt.x * fn; wt.y += vt.y * fn; wt.z += vt.z * fn; wt.w += vt.w * fn;
        pt.x += vt.x;      pt.y += vt.y;      pt.z += vt.z;      pt.w += vt.w;
    }
    int e0 = g4 * 4;
    if (ps.x > 0.5f) g_si[e0 + 0] = (int)(ws.x + 0.5f) + 1;
    if (ps.y > 0.5f) g_si[e0 + 1] = (int)(ws.y + 0.5f) + 1;
    if (ps.z > 0.5f) g_si[e0 + 2] = (int)(ws.z + 0.5f) + 1;
    if (ps.w > 0.5f) g_si[e0 + 3] = (int)(ws.w + 0.5f) + 1;
    if (pt.x > 0.5f) g_ti[e0 + 0] = (int)(wt.x + 0.5f) + 1;
    if (pt.y > 0.5f) g_ti[e0 + 1] = (int)(wt.y + 0.5f) + 1;
    if (pt.z > 0.5f) g_ti[e0 + 2] = (int)(wt.z + 0.5f) + 1;
    if (pt.w > 0.5f) g_ti[e0 + 3] = (int)(wt.w + 0.5f) + 1;
}

// ---------------------------------------------------------------------------
// K2a (k_build1): build adjacency for edges whose BOTH endpoints were found
// in part A (stored value in (0, ROWS_A]). Race-safe vs concurrent part B
// writes: a racing read returns 0 or a value > ROWS_A — both excluded.
// ---------------------------------------------------------------------------
__global__ void __launch_bounds__(256) k_build1() {
    int e = blockIdx.x * blockDim.x + threadIdx.x;
    int si = g_si[e];
    int ti = g_ti[e];
    if (si > 0 && si <= ROWS_A && ti > 0 && ti <= ROWS_A) {
        int t = ti - 1;
        int slot = atomicAdd(&g_cnt[t], 1);
        g_adj[t * CAP + slot] = si - 1;
    }
}

// K2b (k_build2): build the complement (at least one endpoint >= ROWS_A).
__global__ void __launch_bounds__(256) k_build2() {
    int e = blockIdx.x * blockDim.x + threadIdx.x;
    int si = g_si[e];
    int ti = g_ti[e];
    if (si > ROWS_A || ti > ROWS_A) {
        int t = ti - 1;
        int slot = atomicAdd(&g_cnt[t], 1);
        g_adj[t * CAP + slot] = si - 1;
    }
}

// ---------------------------------------------------------------------------
// K3 (k_gather_part): partial gather over phase-1 adjacency. Side stream,
// hidden under scan part B. Block = node, 8 warps stride the list;
// partials to g_pacc/g_pasum; consumed count snapshotted in g_done.
// ---------------------------------------------------------------------------
__global__ void __launch_bounds__(256) k_gather_part(const float* __restrict__ bf) {
    __shared__ float2 sacc[8][32];
    __shared__ float  sasum[8];

    const int warp = threadIdx.x >> 5;
    const int lane = threadIdx.x & 31;
    const int t    = blockIdx.x;
    const int cnt0 = g_cnt[t];

    const int* adj = g_adj + t * CAP;
    const float2* P2 = (const float2*)g_P;

    float2 q = ((const float2*)g_Q)[t * 32 + lane];
    float2 b = __ldg(&((const float2*)bf)[lane]);
    const float c = q.x + b.x;
    const float d = q.y + b.y;

    float2 acc = make_float2(0.f, 0.f);
    float  asum = 0.f;
    for (int k = warp; k < cnt0; k += 8) {
        int s = adj[k];
        float a = g_eu[s];
        float2 p = P2[s * 32 + lane];
        acc.x += a * fmaxf(p.x + c, 0.f);
        acc.y += a * fmaxf(p.y + d, 0.f);
        asum  += a;
    }
    sacc[warp][lane] = acc;
    if (lane == 0) sasum[warp] = asum;
    __syncthreads();

    if (warp == 0) {
        float ax = 0.f, ay = 0.f, as = 0.f;
#pragma unroll
        for (int wb = 0; wb < 8; ++wb) {
            float2 a = sacc[wb][lane];
            ax += a.x; ay += a.y; as += sasum[wb];
        }
        g_pacc[t * 32 + lane] = make_float2(ax, ay);
        if (lane == 0) { g_pasum[t] = as; g_done[t] = cnt0; }
    }
}

// ---------------------------------------------------------------------------
// K4 (k_gather_fin): gather remaining slots [g_done[t], g_cnt[t]), combine
// with saved partials, normalize, write out. Resets g_cnt for next replay.
// evt factored out of the softmax ratio (exact except eps).
// ---------------------------------------------------------------------------
__global__ void __launch_bounds__(256) k_gather_fin(const float* __restrict__ bf,
                                                    const float* __restrict__ bw,
                                                    float* __restrict__ out) {
    __shared__ float2 sacc[8][32];
    __shared__ float  sasum[8];

    const int warp = threadIdx.x >> 5;
    const int lane = threadIdx.x & 31;
    const int t    = blockIdx.x;
    const int done = g_done[t];
    const int deg  = g_cnt[t];

    const int* adj = g_adj + t * CAP;
    const float2* P2 = (const float2*)g_P;

    float2 q = ((const float2*)g_Q)[t * 32 + lane];
    float2 b = __ldg(&((const float2*)bf)[lane]);
    const float c = q.x + b.x;
    const float d = q.y + b.y;

    float2 acc = make_float2(0.f, 0.f);
    float  asum = 0.f;
    for (int k = done + warp; k < deg; k += 8) {
        int s = adj[k];
        float a = g_eu[s];
        float2 p = P2[s * 32 + lane];
        acc.x += a * fmaxf(p.x + c, 0.f);
        acc.y += a * fmaxf(p.y + d, 0.f);
        asum  += a;
    }
    sacc[warp][lane] = acc;
    if (lane == 0) sasum[warp] = asum;
    __syncthreads();

    if (warp == 0) {
        float ax = 0.f, ay = 0.f, as = 0.f;
#pragma unroll
        for (int wb = 0; wb < 8; ++wb) {
            float2 a = sacc[wb][lane];
            ax += a.x; ay += a.y; as += sasum[wb];
        }
        float2 pa = g_pacc[t * 32 + lane];
        ax += pa.x; ay += pa.y; as += g_pasum[t];
        const float evt = expf(g_v[t] + __ldg(bw));
        float inv = evt / (evt * as + EPSV);
        ((float2*)out)[t * 32 + lane] = make_float2(ax * inv, ay * inv);
        if (lane == 0) g_cnt[t] = 0;           // self-clean for next replay
    }
}

// ---------------------------------------------------------------------------
extern "C" void kernel_launch(void* const* d_in, const int* in_sizes, int n_in,
                              void* d_out, int out_size) {
    const float* x   = (const float*)d_in[0];
    const float* src = (const float*)d_in[1];
    const float* tgt = (const float*)d_in[2];
    const float* Wf  = (const float*)d_in[3];
    const float* bf  = (const float*)d_in[4];
    const float* Ww  = (const float*)d_in[5];
    const float* bw  = (const float*)d_in[6];
    float* out = (float*)d_out;

    // side stream + events, created once on the (uncaptured) first call
    static cudaStream_t s2 = nullptr;
    static cudaEvent_t ev_fork = nullptr, ev_a = nullptr, ev_side = nullptr;
    if (s2 == nullptr) {
        cudaStreamCreateWithFlags(&s2, cudaStreamNonBlocking);
        cudaEventCreateWithFlags(&ev_fork, cudaEventDisableTiming);
        cudaEventCreateWithFlags(&ev_a,    cudaEventDisableTiming);
        cudaEventCreateWithFlags(&ev_side, cudaEventDisableTiming);
    }

    // fork: k_pre hidden under scan part A
    cudaEventRecord(ev_fork, 0);
    cudaStreamWaitEvent(s2, ev_fork, 0);
    k_pre<<<NODESN / 64, 256, 0, s2>>>(x, Wf, Ww);

    // main: scan part A (rows 0..1791) — proven tile shape (64,64)
    k_scan_rows<RCA><<<dim3(64, 64), 256>>>((const float4*)src,
                                            (const float4*)tgt, 0);
    cudaEventRecord(ev_a, 0);

    // side: build + partial gather over phase-1 edges, hidden under part B
    cudaStreamWaitEvent(s2, ev_a, 0);
    k_build1<<<EDGES / 256, 256, 0, s2>>>();
    k_gather_part<<<NODESN, 256, 0, s2>>>(bf);
    cudaEventRecord(ev_side, s2);

    // main: scan part B (rows 1792..2047)
    k_scan_rows<RCB><<<dim3(64, 64), 256>>>((const float4*)src,
                                            (const float4*)tgt, ROWS_A);

    // main: finish — build complement, gather remainder + combine
    cudaStreamWaitEvent(0, ev_side, 0);
    k_build2<<<EDGES / 256, 256>>>();
    k_gather_fin<<<NODESN, 256>>>(bf, bw, out);
}

// round 16
// speedup vs baseline: 1.0436x; 1.0436x over previous
#include <cuda_runtime.h>

#define EDGES   65536
#define NODESN  2048
#define DI      64
#define DOUT    64
#define EPSV    1e-6f
#define RCHUNK  32             // rows per scan tile (R6-proven best)
#define CAP     256            // adjacency capacity per node

// scratch (no cudaMalloc allowed). Zero-initialized; g_adj slots >= deg are
// never written (deterministic replays rewrite the same slots), so
// unconditional loads of those slots return a valid (masked-out) value.
__device__ int    g_si[EDGES];          // src index per edge
__device__ int    g_cnt[NODESN];        // per-target count (reset by gather)
__device__ int    g_adj[NODESN * CAP];  // per-target EDGE-ID lists
__device__ float  g_P[NODESN * DOUT];   // x @ Wf_top
__device__ float  g_Q[NODESN * DOUT];   // x @ Wf_bot
__device__ float  g_eu[NODESN];         // exp(x . Ww_top)
__device__ float  g_v[NODESN];          // x . Ww_bot

// ---------------------------------------------------------------------------
// K0 (k_pre): per-node projections P,Q,exp(u),v. Side stream, fully hidden
// under the HBM-bound scan.
// ---------------------------------------------------------------------------
__global__ void __launch_bounds__(256) k_pre(const float* __restrict__ x,
                                             const float* __restrict__ Wf,
                                             const float* __restrict__ Ww) {
    __shared__ float sW[2 * DI * DOUT];   // 32 KB
    __shared__ float sx[DI * 64];         // 16 KB, transposed x tile

    const int tid = threadIdx.x;
    const int n0 = blockIdx.x * 64;

    {
        const float4* Wf4 = (const float4*)Wf;
        float4* sW4 = (float4*)sW;
#pragma unroll
        for (int i = 0; i < 8; ++i)
            sW4[tid + i * 256] = Wf4[tid + i * 256];
    }
    {
        const float4* x4 = (const float4*)x;
#pragma unroll
        for (int i = 0; i < 4; ++i) {
            int idx = tid + i * 256;
            int nl = idx >> 4;
            int kq = idx & 15;
            float4 vv = x4[(n0 + nl) * (DI / 4) + kq];
            sx[(kq * 4 + 0) * 64 + nl] = vv.x;
            sx[(kq * 4 + 1) * 64 + nl] = vv.y;
            sx[(kq * 4 + 2) * 64 + nl] = vv.z;
            sx[(kq * 4 + 3) * 64 + nl] = vv.w;
        }
    }
    __syncthreads();

    const int nl = tid >> 2;
    const int dg = (tid & 3) * 16;

    float accP[16] = {}, accQ[16] = {};
    const float4* sW4 = (const float4*)sW;
#pragma unroll 4
    for (int k = 0; k < DI; ++k) {
        float xv = sx[k * 64 + nl];
        int bP = (k * DOUT + dg) >> 2;
        int bQ = ((DI + k) * DOUT + dg) >> 2;
#pragma unroll
        for (int j = 0; j < 4; ++j) {
            float4 w = sW4[bP + j];
            accP[j * 4 + 0] += xv * w.x; accP[j * 4 + 1] += xv * w.y;
            accP[j * 4 + 2] += xv * w.z; accP[j * 4 + 3] += xv * w.w;
            float4 q = sW4[bQ + j];
            accQ[j * 4 + 0] += xv * q.x; accQ[j * 4 + 1] += xv * q.y;
            accQ[j * 4 + 2] += xv * q.z; accQ[j * 4 + 3] += xv * q.w;
        }
    }
    float4* P4 = (float4*)(g_P + (n0 + nl) * DOUT + dg);
    float4* Q4 = (float4*)(g_Q + (n0 + nl) * DOUT + dg);
#pragma unroll
    for (int j = 0; j < 4; ++j) {
        P4[j] = make_float4(accP[j*4+0], accP[j*4+1], accP[j*4+2], accP[j*4+3]);
        Q4[j] = make_float4(accQ[j*4+0], accQ[j*4+1], accQ[j*4+2], accQ[j*4+3]);
    }

    if (tid < 64) {
        float uu = 0.f, vv = 0.f;
#pragma unroll 8
        for (int k = 0; k < DI; ++k) {
            float xv = sx[k * 64 + tid];
            uu += xv * __ldg(&Ww[k]);
            vv += xv * __ldg(&Ww[DI + k]);
        }
        g_eu[n0 + tid] = expf(uu);
        g_v[n0 + tid]  = vv;
    }
}

// ---------------------------------------------------------------------------
// K1 (k_scan): R6-proven fused streaming scan (two accumulators, RCHUNK=32,
// grid (64,64), float4 .cs loads) with the BUILD absorbed into the epilogue:
// src hits store g_si; tgt hits append the EDGE ID to g_adj (avg 16 atomics
// per block after 32768 streamed loads — negligible vs the HBM stream).
// ---------------------------------------------------------------------------
__global__ void __launch_bounds__(256) k_scan(const float4* __restrict__ src4,
                                              const float4* __restrict__ tgt4) {
    const int g4 = blockIdx.x * blockDim.x + threadIdx.x;
    const int r0 = blockIdx.y * RCHUNK;
    const int stride4 = EDGES / 4;                          // 16384
    size_t base = (size_t)r0 * stride4 + g4;

    float4 ws = {0.f,0.f,0.f,0.f}, wt = {0.f,0.f,0.f,0.f};  // sum n*v
    float4 ps = {0.f,0.f,0.f,0.f}, pt = {0.f,0.f,0.f,0.f};  // sum v

#pragma unroll 8
    for (int n = 0; n < RCHUNK; ++n) {
        float fn = (float)(r0 + n);
        float4 vs = __ldcs(&src4[base]);
        float4 vt = __ldcs(&tgt4[base]);
        base += stride4;
        ws.x += vs.x * fn; ws.y += vs.y * fn; ws.z += vs.z * fn; ws.w += vs.w * fn;
        ps.x += vs.x;      ps.y += vs.y;      ps.z += vs.z;      ps.w += vs.w;
        wt.x += vt.x * fn; wt.y += vt.y * fn; wt.z += vt.z * fn; wt.w += vt.w * fn;
        pt.x += vt.x;      pt.y += vt.y;      pt.z += vt.z;      pt.w += vt.w;
    }
    int e0 = g4 * 4;
    if (ps.x > 0.5f) g_si[e0 + 0] = (int)(ws.x + 0.5f);
    if (ps.y > 0.5f) g_si[e0 + 1] = (int)(ws.y + 0.5f);
    if (ps.z > 0.5f) g_si[e0 + 2] = (int)(ws.z + 0.5f);
    if (ps.w > 0.5f) g_si[e0 + 3] = (int)(ws.w + 0.5f);
    if (pt.x > 0.5f) { int t = (int)(wt.x + 0.5f);
        g_adj[t * CAP + atomicAdd(&g_cnt[t], 1)] = e0 + 0; }
    if (pt.y > 0.5f) { int t = (int)(wt.y + 0.5f);
        g_adj[t * CAP + atomicAdd(&g_cnt[t], 1)] = e0 + 1; }
    if (pt.z > 0.5f) { int t = (int)(wt.z + 0.5f);
        g_adj[t * CAP + atomicAdd(&g_cnt[t], 1)] = e0 + 2; }
    if (pt.w > 0.5f) { int t = (int)(wt.w + 0.5f);
        g_adj[t * CAP + atomicAdd(&g_cnt[t], 1)] = e0 + 3; }
}

// ---------------------------------------------------------------------------
// K2 (k_gather): 8 warps per node, lane = 2 dims. Fully BATCHED 3-level
// chain: 8 adj (edge ids) -> 8 g_si -> 8 eu + 8 P2, each level issued
// back-to-back. Slots >= deg are masked at accumulate time (zero-init /
// deterministic-replay safe). Cleanup loop guards deg > 64 (prob ~0).
// evt factored out of the softmax ratio (exact except eps). Resets g_cnt.
// ---------------------------------------------------------------------------
__global__ void __launch_bounds__(256) k_gather(const float* __restrict__ bf,
                                                const float* __restrict__ bw,
                                                float* __restrict__ out) {
    __shared__ float2 sacc[8][32];
    __shared__ float  sasum[8];

    const int warp = threadIdx.x >> 5;        // 0..7
    const int lane = threadIdx.x & 31;
    const int t    = blockIdx.x;
    const int deg  = g_cnt[t];

    const int* adj = g_adj + t * CAP;
    const float2* P2 = (const float2*)g_P;

    float2 q = ((const float2*)g_Q)[t * 32 + lane];
    float2 b = __ldg(&((const float2*)bf)[lane]);
    const float c = q.x + b.x;
    const float d = q.y + b.y;

    // level 1: adjacency (edge ids), 8 independent loads
    int eidx[8];
#pragma unroll
    for (int j = 0; j < 8; ++j)
        eidx[j] = adj[warp + j * 8];
    // level 2: source ids, 8 independent loads
    int sidx[8];
#pragma unroll
    for (int j = 0; j < 8; ++j)
        sidx[j] = g_si[eidx[j]];
    // level 3: eu and P, 16 independent loads
    float aexp[8];
    float2 pv[8];
#pragma unroll
    for (int j = 0; j < 8; ++j)
        aexp[j] = g_eu[sidx[j]];
#pragma unroll
    for (int j = 0; j < 8; ++j)
        pv[j] = P2[sidx[j] * 32 + lane];

    float2 acc = make_float2(0.f, 0.f);
    float  asum = 0.f;
#pragma unroll
    for (int j = 0; j < 8; ++j) {
        float a = (warp + j * 8 < deg) ? aexp[j] : 0.f;
        acc.x += a * fmaxf(pv[j].x + c, 0.f);
        acc.y += a * fmaxf(pv[j].y + d, 0.f);
        asum  += a;
    }
    // correctness guard for deg > 64 (statistically negligible)
    for (int k = 64 + warp; k < deg; k += 8) {
        int s = g_si[adj[k]];
        float a = g_eu[s];
        float2 p = P2[s * 32 + lane];
        acc.x += a * fmaxf(p.x + c, 0.f);
        acc.y += a * fmaxf(p.y + d, 0.f);
        asum  += a;
    }

    sacc[warp][lane] = acc;
    if (lane == 0) sasum[warp] = asum;
    __syncthreads();

    if (warp == 0) {
        float ax = 0.f, ay = 0.f, as = 0.f;
#pragma unroll
        for (int wb = 0; wb < 8; ++wb) {
            float2 a = sacc[wb][lane];
            ax += a.x; ay += a.y; as += sasum[wb];
        }
        const float evt = expf(g_v[t] + __ldg(bw));
        float inv = evt / (evt * as + EPSV);
        ((float2*)out)[t * 32 + lane] = make_float2(ax * inv, ay * inv);
        if (lane == 0) g_cnt[t] = 0;           // self-clean for next replay
    }
}

// ---------------------------------------------------------------------------
extern "C" void kernel_launch(void* const* d_in, const int* in_sizes, int n_in,
                              void* d_out, int out_size) {
    const float* x   = (const float*)d_in[0];
    const float* src = (const float*)d_in[1];
    const float* tgt = (const float*)d_in[2];
    const float* Wf  = (const float*)d_in[3];
    const float* bf  = (const float*)d_in[4];
    const float* Ww  = (const float*)d_in[5];
    const float* bw  = (const float*)d_in[6];
    float* out = (float*)d_out;

    // side stream + events, created once on the (uncaptured) first call
    static cudaStream_t s2 = nullptr;
    static cudaEvent_t ev_fork = nullptr, ev_join = nullptr;
    if (s2 == nullptr) {
        cudaStreamCreateWithFlags(&s2, cudaStreamNonBlocking);
        cudaEventCreateWithFlags(&ev_fork, cudaEventDisableTiming);
        cudaEventCreateWithFlags(&ev_join, cudaEventDisableTiming);
    }

    // fork: k_pre (projections) hidden under the HBM-bound scan
    cudaEventRecord(ev_fork, 0);
    cudaStreamWaitEvent(s2, ev_fork, 0);
    k_pre<<<NODESN / 64, 256, 0, s2>>>(x, Wf, Ww);
    cudaEventRecord(ev_join, s2);

    // scan with integrated adjacency build
    k_scan<<<dim3(EDGES / 4 / 256, NODESN / RCHUNK), 256>>>(
        (const float4*)src, (const float4*)tgt);

    // join: gather needs scan (g_si, adjacency) and pre (P,Q,eu,v)
    cudaStreamWaitEvent(0, ev_join, 0);
    k_gather<<<NODESN, 256>>>(bf, bw, out);
}